// round 15
// baseline (speedup 1.0000x reference)
#include <cuda_runtime.h>
#include <math.h>
#include <stdint.h>

// Problem constants
#define Bc   4
#define Sc   1024
#define HIDc 1024
#define Hc   16
#define Dc   64

// Scratch for Q, K, V in [B,H,S,D] layout (16 MB each)
__device__ float g_q[Bc * Hc * Sc * Dc];
__device__ float g_k[Bc * Hc * Sc * Dc];
__device__ float g_v[Bc * Hc * Sc * Dc];
// dist_emb as packed bf16x2 pairs: [2047 rows][32 words]
__device__ uint32_t g_ebf[2047 * 32];

typedef unsigned long long ull;

__device__ __forceinline__ ull pk2(float lo, float hi) {
    ull r;
    asm("mov.b64 %0, {%1, %2};" : "=l"(r) : "f"(lo), "f"(hi));
    return r;
}
__device__ __forceinline__ void upk2(float& lo, float& hi, ull v) {
    asm("mov.b64 {%0, %1}, %2;" : "=f"(lo), "=f"(hi) : "l"(v));
}
__device__ __forceinline__ void fma2(ull& d, ull a, ull b) {
    asm("fma.rn.f32x2 %0, %1, %2, %0;" : "+l"(d) : "l"(a), "l"(b));
}
// bf16x2 word -> f32x2 pair (lo = low half)
__device__ __forceinline__ ull bf2e(uint32_t w) {
    uint32_t lo = w << 16;
    uint32_t hi = w & 0xFFFF0000u;
    ull r;
    asm("mov.b64 %0, {%1, %2};" : "=l"(r) : "r"(lo), "r"(hi));
    return r;
}
__device__ __forceinline__ uint32_t smem_u32(const void* p) {
    uint32_t a;
    asm("{ .reg .u64 t; cvta.to.shared.u64 t, %1; cvt.u32.u64 %0, t; }"
        : "=r"(a) : "l"(p));
    return a;
}
__device__ __forceinline__ void cpa4(uint32_t dst, const void* src) {
    asm volatile("cp.async.ca.shared.global [%0], [%1], 4;"
                 :: "r"(dst), "l"(src) : "memory");
}
__device__ __forceinline__ void cpa8(uint32_t dst, const void* src) {
    asm volatile("cp.async.ca.shared.global [%0], [%1], 8;"
                 :: "r"(dst), "l"(src) : "memory");
}
#define CPA_COMMIT() asm volatile("cp.async.commit_group;" ::: "memory")
#define CPA_WAIT0()  asm volatile("cp.async.wait_group 0;" ::: "memory")

// ---------------------------------------------------------------------------
// dist_emb -> bf16x2 pre-conversion (one-time, ~65K words)
// ---------------------------------------------------------------------------
__global__ void conv_ebf(const float* __restrict__ de)
{
    int idx = blockIdx.x * 256 + threadIdx.x;
    if (idx < 2047 * 32) {
        int r  = idx >> 5;
        int d2 = idx & 31;
        uint32_t wa = __float_as_uint(de[r * 64 + 2 * d2]);
        uint32_t wb = __float_as_uint(de[r * 64 + 2 * d2 + 1]);
        uint32_t ba = (wa + 0x7FFFu + ((wa >> 16) & 1u)) >> 16;   // RNE bf16
        uint32_t bb = (wb + 0x7FFFu + ((wb >> 16) & 1u)) >> 16;
        g_ebf[idx] = (bb << 16) | (ba & 0xFFFFu);
    }
}

// ---------------------------------------------------------------------------
// Kernel A: projection GEMM  C = X @ W + bias, scattered to [B,H,S,D]
// (proven scalar version — at the FFMA roofline)
// ---------------------------------------------------------------------------
__global__ __launch_bounds__(256) void gemm_proj(const float* __restrict__ X,
                                                 const float* __restrict__ W,
                                                 const float* __restrict__ bias,
                                                 int which)
{
    __shared__ float As[16][132];
    __shared__ float Bs[16][132];
    float* outp = (which == 0) ? g_q : (which == 1) ? g_k : g_v;

    const int tid = threadIdx.x;
    const int m0  = blockIdx.y * 128;
    const int n0  = blockIdx.x * 128;
    const int ty  = tid >> 4;
    const int tx  = tid & 15;

    float acc[8][8];
#pragma unroll
    for (int i = 0; i < 8; i++)
#pragma unroll
        for (int j = 0; j < 8; j++) acc[i][j] = 0.f;

    for (int k0 = 0; k0 < 1024; k0 += 16) {
#pragma unroll
        for (int i = 0; i < 2; i++) {
            int f   = tid + i * 256;
            int row = f >> 2;
            int kc  = (f & 3) << 2;
            float4 va = *(const float4*)(X + (size_t)(m0 + row) * 1024 + k0 + kc);
            As[kc + 0][row] = va.x;
            As[kc + 1][row] = va.y;
            As[kc + 2][row] = va.z;
            As[kc + 3][row] = va.w;
        }
#pragma unroll
        for (int i = 0; i < 2; i++) {
            int f  = tid + i * 256;
            int kr = f >> 5;
            int nc = (f & 31) << 2;
            *(float4*)&Bs[kr][nc] =
                *(const float4*)(W + (size_t)(k0 + kr) * 1024 + n0 + nc);
        }
        __syncthreads();

#pragma unroll
        for (int kk = 0; kk < 16; kk++) {
            float a[8], b[8];
            *(float4*)&a[0] = *(const float4*)&As[kk][ty * 8];
            *(float4*)&a[4] = *(const float4*)&As[kk][ty * 8 + 4];
            *(float4*)&b[0] = *(const float4*)&Bs[kk][tx * 8];
            *(float4*)&b[4] = *(const float4*)&Bs[kk][tx * 8 + 4];
#pragma unroll
            for (int i = 0; i < 8; i++)
#pragma unroll
                for (int j = 0; j < 8; j++)
                    acc[i][j] += a[i] * b[j];
        }
        __syncthreads();
    }

#pragma unroll
    for (int i = 0; i < 8; i++) {
        int m = m0 + ty * 8 + i;
        int b = m >> 10;
        int s = m & 1023;
#pragma unroll
        for (int j = 0; j < 8; j++) {
            int n = n0 + tx * 8 + j;
            int h = n >> 6;
            int d = n & 63;
            outp[(((size_t)(b * Hc + h)) * Sc + s) * Dc + d] = acc[i][j] + bias[n];
        }
    }
}

// ---------------------------------------------------------------------------
// Kernel B: fused attention. 64x64 tiles, 8x4 micro-tile, 128 threads.
// E as bf16x2: word(r,d2) = r*33 + (r>>2) + d2  -> 1-phase e loads.
// K rows: rot = 2*((r>>2)&15).  V/P columns: +2*(col>>5) swizzle.
// cp.async pipelining (K/E during softmax+PV, V after PV).
// ---------------------------------------------------------------------------
#define ROTK(r) ((((r) >> 2) & 15) << 1)

#define QOFF  0                     // 64 x 68                    = 4352
#define KOFF  4352                  // 64 x 68 + 32 rot           = 4384
#define VOFF  8736                  // 64 x 68 (col swizzle)      = 4352
#define EOFF  13088                 // bf16x2: 127*33 + 31 + 32   = 4254 words
#define POFF  17342                 // 64 x 66 (col swizzle)      = 4224
#define DNOFF 21566                 // 64
#define AMOFF 21630                 // 1024 (am + log-mask fused)
#define SMEMF 22654
#define ATTN_SMEM_BYTES (SMEMF * 4) // 90616 B (2 CTAs/SM)

__global__ __launch_bounds__(128) void attn_kernel(const float* __restrict__ attn_mask,
                                                   const int*   __restrict__ skim,
                                                   float*       __restrict__ out)
{
    extern __shared__ float smf[];
    uint32_t* smu = (uint32_t*)smf;
    const uint32_t smb = smem_u32(smf);
    const int tid = threadIdx.x;
    const int l0  = blockIdx.x * 64;
    const int bh  = blockIdx.y;
    const int b   = bh >> 4;
    const int h   = bh & 15;
    const int ty  = tid >> 4;   // 0..7  -> 8 query rows each
    const int tx  = tid & 15;   // 0..15 -> 4 key cols each

    const float* q = g_q + (size_t)bh * Sc * Dc;
    const float* k = g_k + (size_t)bh * Sc * Dc;
    const float* v = g_v + (size_t)bh * Sc * Dc;

    // ---- async copy emitters ----
    auto issue_KE = [&](int r0n) {
        const float* ksrc = k + (size_t)r0n * 64;
#pragma unroll
        for (int i = 0; i < 16; i++) {       // K: 64 rows x 32 8B-units
            int u   = tid + i * 128;
            int row = u >> 5;
            int c2  = (u & 31) << 1;
            uint32_t dst = smb + (uint32_t)(KOFF + row * 68 + ROTK(row) + c2) * 4;
            cpa8(dst, ksrc + row * 64 + c2);
        }
        const uint32_t* esrc = g_ebf + (size_t)(l0 - r0n + 960) * 32;
#pragma unroll
        for (int i = 0; i < 32; i++) {       // E: 127 rows x 32 4B words
            int u = tid + i * 128;
            if (u < 4064) {
                int row = u >> 5;
                int w   = u & 31;
                uint32_t dst = smb + (uint32_t)(EOFF + row * 33 + (row >> 2) + w) * 4;
                cpa4(dst, esrc + row * 32 + w);
            }
        }
        CPA_COMMIT();
    };
    auto issue_V = [&](int r0n) {
        const float* vsrc = v + (size_t)r0n * 64;
#pragma unroll
        for (int i = 0; i < 16; i++) {       // V: 64 rows x 32 8B-units, col swizzle
            int u   = tid + i * 128;
            int row = u >> 5;
            int c2  = (u & 31) << 1;
            uint32_t dst = smb + (uint32_t)(VOFF + row * 68 + c2 + ((c2 >> 5) << 1)) * 4;
            cpa8(dst, vsrc + row * 64 + c2);
        }
        CPA_COMMIT();
    };

    // ---- prologue ----
    issue_KE(0);
    issue_V(0);
#pragma unroll
    for (int i = 0; i < 8; i++) {
        int f   = tid + i * 128;       // 0..1023 float4s
        int row = f >> 4;
        int c4  = (f & 15) << 2;
        float4 val = *(const float4*)(q + (size_t)(l0 + row) * 64 + c4);
        *(float4*)&smf[QOFF + row * 68 + c4] = val;
    }
#pragma unroll
    for (int i = 0; i < 8; i++) {
        int f = tid + i * 128;
        float am = attn_mask[b * Sc + f];
        smf[AMOFF + f] = am + (skim[b * Sc + f] ? 0.f : -1e30f);
    }
    if (tid < 64) smf[DNOFF + tid] = 0.f;
    CPA_WAIT0();
    __syncthreads();

    ull pv2[8][2];
#pragma unroll
    for (int i = 0; i < 8; i++) { pv2[i][0] = 0ull; pv2[i][1] = 0ull; }

    // Hoisted base addresses (chunk-invariant)
    const int jb0 = ty * 8 - tx * 4 + 60;      // in [0,116]
    int ebt[11];
#pragma unroll
    for (int t = 0; t < 11; t++) {
        int r = jb0 + t;                        // in [0,126]
        ebt[t] = EOFF + r * 33 + (r >> 2);
    }
    const int qb  = QOFF + ty * 8 * 68;
    const int kb  = KOFF + tx * 4 * 68 + (tx << 1);       // ROTK(4*tx) = 2*tx
    const int txo = tx * 4 + ((tx >> 3) << 1);            // V col swizzle
    const int pco = tx * 4 + ((tx >> 3) << 1);            // P col swizzle (cols=rr)

    for (int c = 0; c < 16; c++) {
        // ---- Scores: s[il][ir] = sum_d q*k + q*e (bf16), f32x2 over d-pairs
        ull s2[8][4];
#pragma unroll
        for (int i = 0; i < 8; i++)
#pragma unroll
            for (int j = 0; j < 4; j++) s2[i][j] = 0ull;

#pragma unroll 2
        for (int d2 = 0; d2 < 32; d2++) {
            const int d = d2 << 1;
            ull q2[8], k2[4], e2[11];
#pragma unroll
            for (int il = 0; il < 8; il++)
                q2[il] = *(const ull*)&smf[qb + il * 68 + d];
#pragma unroll
            for (int ir = 0; ir < 4; ir++)
                k2[ir] = *(const ull*)&smf[kb + ir * 68 + d];
#pragma unroll
            for (int t = 0; t < 11; t++)
                e2[t] = bf2e(smu[ebt[t] + d2]);
#pragma unroll
            for (int il = 0; il < 8; il++)
#pragma unroll
                for (int ir = 0; ir < 4; ir++) {
                    fma2(s2[il][ir], q2[il], k2[ir]);
                    fma2(s2[il][ir], q2[il], e2[il - ir + 3]);
                }
        }
        __syncthreads();                 // all warps done reading K,E
        if (c < 15) issue_KE((c + 1) * 64);   // overlaps softmax + PV

        // ---- probs = exp(s/8 + amsk); store P (swizzled); accumulate denoms
        const int amb = AMOFF + c * 64 + tx * 4;
#pragma unroll
        for (int il = 0; il < 8; il++) {
            int l = ty * 8 + il;
            float rs = 0.f;
            float pr[4];
#pragma unroll
            for (int ir = 0; ir < 4; ir++) {
                float lo, hi;
                upk2(lo, hi, s2[il][ir]);
                float p = __expf((lo + hi) * 0.125f + smf[amb + ir]);
                pr[ir] = p;
                rs += p;
            }
            *(float2*)&smf[POFF + l * 66 + pco]     = make_float2(pr[0], pr[1]);
            *(float2*)&smf[POFF + l * 66 + pco + 2] = make_float2(pr[2], pr[3]);
            rs += __shfl_xor_sync(0xffffffffu, rs, 1);
            rs += __shfl_xor_sync(0xffffffffu, rs, 2);
            rs += __shfl_xor_sync(0xffffffffu, rs, 4);
            rs += __shfl_xor_sync(0xffffffffu, rs, 8);
            if (tx == 0) smf[DNOFF + l] += rs;
        }
        __syncwarp();   // this warp's P rows (its own ty) fully written

        // ---- PV: rr-pairs; P pair loaded 64-bit (swizzled cols), dup in regs
#pragma unroll 2
        for (int rr2 = 0; rr2 < 32; rr2++) {
            const int rr  = rr2 << 1;
            const int rro = rr + ((rr >> 5) << 1);    // P col swizzle for rr
            ull v00 = *(const ull*)&smf[VOFF + rr * 68 + txo];
            ull v01 = *(const ull*)&smf[VOFF + rr * 68 + txo + 2];
            ull v10 = *(const ull*)&smf[VOFF + (rr + 1) * 68 + txo];
            ull v11 = *(const ull*)&smf[VOFF + (rr + 1) * 68 + txo + 2];
#pragma unroll
            for (int il = 0; il < 8; il++) {
                ull p2 = *(const ull*)&smf[POFF + (ty * 8 + il) * 66 + rro];
                float pa, pb;
                upk2(pa, pb, p2);
                ull pa2 = pk2(pa, pa);
                ull pb2 = pk2(pb, pb);
                fma2(pv2[il][0], pa2, v00);
                fma2(pv2[il][1], pa2, v01);
                fma2(pv2[il][0], pb2, v10);
                fma2(pv2[il][1], pb2, v11);
            }
        }
        __syncthreads();                 // all warps done reading V (and P)
        if (c < 15) issue_V((c + 1) * 64);
        CPA_WAIT0();                     // K',E',V' landed
        __syncthreads();
    }

    // ---- write out: out[b, l, h*64 + d] = acc / (eps + denom)
#pragma unroll
    for (int il = 0; il < 8; il++) {
        int l = l0 + ty * 8 + il;
        float dinv = 1.f / (1e-8f + smf[DNOFF + ty * 8 + il]);
        float a0, a1, a2_, a3;
        upk2(a0, a1, pv2[il][0]);
        upk2(a2_, a3, pv2[il][1]);
        float4 o = make_float4(a0 * dinv, a1 * dinv, a2_ * dinv, a3 * dinv);
        *(float4*)&out[((size_t)(b * Sc + l)) * HIDc + h * 64 + tx * 4] = o;
    }
}

// ---------------------------------------------------------------------------
extern "C" void kernel_launch(void* const* d_in, const int* in_sizes, int n_in,
                              void* d_out, int out_size)
{
    const float* hidden = (const float*)d_in[0];
    const float* amask  = (const float*)d_in[1];
    const int*   skim   = (const int*)  d_in[2];
    const float* Wq     = (const float*)d_in[3];
    const float* bq     = (const float*)d_in[4];
    const float* Wk     = (const float*)d_in[5];
    const float* bk     = (const float*)d_in[6];
    const float* Wv     = (const float*)d_in[7];
    const float* bv     = (const float*)d_in[8];
    const float* demb   = (const float*)d_in[9];
    float* out = (float*)d_out;

    conv_ebf<<<256, 256>>>(demb);

    dim3 ggrid(8, 32);   // N/128, M/128
    gemm_proj<<<ggrid, 256>>>(hidden, Wq, bq, 0);
    gemm_proj<<<ggrid, 256>>>(hidden, Wk, bk, 1);
    gemm_proj<<<ggrid, 256>>>(hidden, Wv, bv, 2);

    cudaFuncSetAttribute(attn_kernel,
                         cudaFuncAttributeMaxDynamicSharedMemorySize,
                         ATTN_SMEM_BYTES);
    dim3 agrid(Sc / 64, Bc * Hc);
    attn_kernel<<<agrid, 128, ATTN_SMEM_BYTES>>>(amask, skim, out);
}

// round 16
// speedup vs baseline: 1.0102x; 1.0102x over previous
#include <cuda_runtime.h>
#include <math.h>
#include <stdint.h>

// Problem constants
#define Bc   4
#define Sc   1024
#define HIDc 1024
#define Hc   16
#define Dc   64

// Scratch for Q, K, V in [B,H,S,D] layout (16 MB each)
__device__ float g_q[Bc * Hc * Sc * Dc];
__device__ float g_k[Bc * Hc * Sc * Dc];
__device__ float g_v[Bc * Hc * Sc * Dc];

typedef unsigned long long ull;

__device__ __forceinline__ ull pk2(float lo, float hi) {
    ull r;
    asm("mov.b64 %0, {%1, %2};" : "=l"(r) : "f"(lo), "f"(hi));
    return r;
}
__device__ __forceinline__ void upk2(float& lo, float& hi, ull v) {
    asm("mov.b64 {%0, %1}, %2;" : "=f"(lo), "=f"(hi) : "l"(v));
}
__device__ __forceinline__ void fma2(ull& d, ull a, ull b) {
    asm("fma.rn.f32x2 %0, %1, %2, %0;" : "+l"(d) : "l"(a), "l"(b));
}
__device__ __forceinline__ uint32_t smem_u32(const void* p) {
    uint32_t a;
    asm("{ .reg .u64 t; cvta.to.shared.u64 t, %1; cvt.u32.u64 %0, t; }"
        : "=r"(a) : "l"(p));
    return a;
}
__device__ __forceinline__ void cpa8(uint32_t dst, const void* src) {
    asm volatile("cp.async.ca.shared.global [%0], [%1], 8;"
                 :: "r"(dst), "l"(src) : "memory");
}
__device__ __forceinline__ void cpa16(uint32_t dst, const void* src) {
    asm volatile("cp.async.cg.shared.global [%0], [%1], 16;"
                 :: "r"(dst), "l"(src) : "memory");
}
#define CPA_COMMIT() asm volatile("cp.async.commit_group;" ::: "memory")
#define CPA_WAIT0()  asm volatile("cp.async.wait_group 0;" ::: "memory")

// ---------------------------------------------------------------------------
// Kernel A: projection GEMM  C = X @ W + bias, scattered to [B,H,S,D]
// (proven scalar version — at the FFMA roofline, ~95% of pipe peak)
// ---------------------------------------------------------------------------
__global__ __launch_bounds__(256) void gemm_proj(const float* __restrict__ X,
                                                 const float* __restrict__ W,
                                                 const float* __restrict__ bias,
                                                 int which)
{
    __shared__ float As[16][132];
    __shared__ float Bs[16][132];
    float* outp = (which == 0) ? g_q : (which == 1) ? g_k : g_v;

    const int tid = threadIdx.x;
    const int m0  = blockIdx.y * 128;
    const int n0  = blockIdx.x * 128;
    const int ty  = tid >> 4;
    const int tx  = tid & 15;

    float acc[8][8];
#pragma unroll
    for (int i = 0; i < 8; i++)
#pragma unroll
        for (int j = 0; j < 8; j++) acc[i][j] = 0.f;

    for (int k0 = 0; k0 < 1024; k0 += 16) {
#pragma unroll
        for (int i = 0; i < 2; i++) {
            int f   = tid + i * 256;
            int row = f >> 2;
            int kc  = (f & 3) << 2;
            float4 va = *(const float4*)(X + (size_t)(m0 + row) * 1024 + k0 + kc);
            As[kc + 0][row] = va.x;
            As[kc + 1][row] = va.y;
            As[kc + 2][row] = va.z;
            As[kc + 3][row] = va.w;
        }
#pragma unroll
        for (int i = 0; i < 2; i++) {
            int f  = tid + i * 256;
            int kr = f >> 5;
            int nc = (f & 31) << 2;
            *(float4*)&Bs[kr][nc] =
                *(const float4*)(W + (size_t)(k0 + kr) * 1024 + n0 + nc);
        }
        __syncthreads();

#pragma unroll
        for (int kk = 0; kk < 16; kk++) {
            float a[8], b[8];
            *(float4*)&a[0] = *(const float4*)&As[kk][ty * 8];
            *(float4*)&a[4] = *(const float4*)&As[kk][ty * 8 + 4];
            *(float4*)&b[0] = *(const float4*)&Bs[kk][tx * 8];
            *(float4*)&b[4] = *(const float4*)&Bs[kk][tx * 8 + 4];
#pragma unroll
            for (int i = 0; i < 8; i++)
#pragma unroll
                for (int j = 0; j < 8; j++)
                    acc[i][j] += a[i] * b[j];
        }
        __syncthreads();
    }

#pragma unroll
    for (int i = 0; i < 8; i++) {
        int m = m0 + ty * 8 + i;
        int b = m >> 10;
        int s = m & 1023;
#pragma unroll
        for (int j = 0; j < 8; j++) {
            int n = n0 + tx * 8 + j;
            int h = n >> 6;
            int d = n & 63;
            outp[(((size_t)(b * Hc + h)) * Sc + s) * Dc + d] = acc[i][j] + bias[n];
        }
    }
}

// ---------------------------------------------------------------------------
// Kernel B: fused attention. 64x64 tiles, 4x4 micro-tile, 256 threads
// (16 warps/SM at 2 CTAs). fp32 E with R14 monotone rotation, f32x2 packed
// FMAs, cp.async pipelining, fused amsk, P/V column swizzles.
// ---------------------------------------------------------------------------
#define ROTK(r) ((((r) >> 2) & 15) << 1)
#define ROTE(r) ((((r) >> 2) & 31) << 1)

#define QOFF  0                     // 64 x 68                 = 4352
#define KOFF  4352                  // 64 x 68 + 32 rot        = 4384
#define VOFF  8736                  // 64 x 68 (col swizzle)   = 4352
#define EOFF  13088                 // 127 x 68 + 64 rot       = 8700
#define POFF  21788                 // 64 x 66 (col swizzle)   = 4224
#define DNOFF 26012                 // 64
#define AMOFF 26076                 // 1024 (am + log-mask fused)
#define SMEMF 27100
#define ATTN_SMEM_BYTES (SMEMF * 4) // 108400 B (2 CTAs/SM -> 16 warps)

__global__ __launch_bounds__(256, 2)
void attn_kernel(const float* __restrict__ attn_mask,
                 const int*   __restrict__ skim,
                 const float* __restrict__ dist_emb,
                 float*       __restrict__ out)
{
    extern __shared__ float smf[];
    const uint32_t smb = smem_u32(smf);
    const int tid = threadIdx.x;
    const int l0  = blockIdx.x * 64;
    const int bh  = blockIdx.y;
    const int b   = bh >> 4;
    const int h   = bh & 15;
    const int ty  = tid >> 4;   // 0..15 -> 4 query rows each
    const int tx  = tid & 15;   // 0..15 -> 4 key cols each

    const float* q = g_q + (size_t)bh * Sc * Dc;
    const float* k = g_k + (size_t)bh * Sc * Dc;
    const float* v = g_v + (size_t)bh * Sc * Dc;

    // ---- async copy emitters (all 256 threads participate) ----
    auto issue_KE = [&](int r0n) {
        const float* ksrc = k + (size_t)r0n * 64;
#pragma unroll
        for (int i = 0; i < 8; i++) {        // K: 64 rows x 32 8B-units
            int u   = tid + i * 256;
            int row = u >> 5;
            int c2  = (u & 31) << 1;
            uint32_t dst = smb + (uint32_t)(KOFF + row * 68 + ROTK(row) + c2) * 4;
            cpa8(dst, ksrc + row * 64 + c2);
        }
        const float* esrc = dist_emb + (size_t)(l0 - r0n + 960) * 64;
#pragma unroll
        for (int i = 0; i < 16; i++) {       // E: 127 rows x 32 8B-units
            int u = tid + i * 256;
            if (u < 4064) {
                int row = u >> 5;
                int c2  = (u & 31) << 1;
                uint32_t dst = smb + (uint32_t)(EOFF + row * 68 + ROTE(row) + c2) * 4;
                cpa8(dst, esrc + (size_t)row * 64 + c2);
            }
        }
        CPA_COMMIT();
    };
    auto issue_V = [&](int r0n) {
        const float* vsrc = v + (size_t)r0n * 64;
#pragma unroll
        for (int i = 0; i < 8; i++) {        // V: 64 rows x 32 8B-units, col swizzle
            int u   = tid + i * 256;
            int row = u >> 5;
            int c2  = (u & 31) << 1;
            uint32_t dst = smb + (uint32_t)(VOFF + row * 68 + c2 + ((c2 >> 5) << 1)) * 4;
            cpa8(dst, vsrc + row * 64 + c2);
        }
        CPA_COMMIT();
    };

    // ---- prologue: chunk-0 K/E/V async, Q tile, fused amsk row ----
    issue_KE(0);
    issue_V(0);
#pragma unroll
    for (int i = 0; i < 4; i++) {
        int f   = tid + i * 256;       // 0..1023 float4s
        int row = f >> 4;
        int c4  = (f & 15) << 2;
        float4 val = *(const float4*)(q + (size_t)(l0 + row) * 64 + c4);
        *(float4*)&smf[QOFF + row * 68 + c4] = val;
    }
#pragma unroll
    for (int i = 0; i < 4; i++) {
        int f = tid + i * 256;
        float am = attn_mask[b * Sc + f];
        smf[AMOFF + f] = am + (skim[b * Sc + f] ? 0.f : -1e30f);
    }
    if (tid < 64) smf[DNOFF + tid] = 0.f;
    CPA_WAIT0();
    __syncthreads();

    ull pv2[4][2];                 // PV acc: pairs along d
#pragma unroll
    for (int i = 0; i < 4; i++) { pv2[i][0] = 0ull; pv2[i][1] = 0ull; }

    // Hoisted base addresses (chunk-invariant)
    const int jb0 = 4 * (ty - tx) + 60;        // in [0,120]
    int ebt[7];
#pragma unroll
    for (int t = 0; t < 7; t++) {
        int r = jb0 + t;                        // in [0,126]
        ebt[t] = EOFF + r * 68 + ROTE(r);
    }
    const int qb  = QOFF + ty * 4 * 68;
    const int kb  = KOFF + tx * 4 * 68 + (tx << 1);   // ROTK(4*tx) = 2*tx
    const int txo = tx * 4 + ((tx >> 3) << 1);        // V col swizzle
    const int pco = tx * 4 + ((tx >> 3) << 1);        // P col swizzle

    for (int c = 0; c < 16; c++) {
        // ---- Scores: s[il][ir] = sum_d q*k + q*e, f32x2 over d-pairs
        ull s2[4][4];
#pragma unroll
        for (int i = 0; i < 4; i++)
#pragma unroll
            for (int j = 0; j < 4; j++) s2[i][j] = 0ull;

#pragma unroll 2
        for (int d2 = 0; d2 < 32; d2++) {
            const int d = d2 << 1;
            ull q2[4], k2[4], e2[7];
#pragma unroll
            for (int il = 0; il < 4; il++)
                q2[il] = *(const ull*)&smf[qb + il * 68 + d];
#pragma unroll
            for (int ir = 0; ir < 4; ir++)
                k2[ir] = *(const ull*)&smf[kb + ir * 68 + d];
#pragma unroll
            for (int t = 0; t < 7; t++)
                e2[t] = *(const ull*)&smf[ebt[t] + d];
#pragma unroll
            for (int il = 0; il < 4; il++)
#pragma unroll
                for (int ir = 0; ir < 4; ir++) {
                    fma2(s2[il][ir], q2[il], k2[ir]);
                    fma2(s2[il][ir], q2[il], e2[il - ir + 3]);
                }
        }
        __syncthreads();                 // all warps done reading K,E
        if (c < 15) issue_KE((c + 1) * 64);   // overlaps softmax + PV

        // ---- probs = exp(s/8 + amsk); store P (swizzled); accumulate denoms
        const int amb = AMOFF + c * 64 + tx * 4;
#pragma unroll
        for (int il = 0; il < 4; il++) {
            int l = ty * 4 + il;
            float rs = 0.f;
            float pr[4];
#pragma unroll
            for (int ir = 0; ir < 4; ir++) {
                float lo, hi;
                upk2(lo, hi, s2[il][ir]);
                float p = __expf((lo + hi) * 0.125f + smf[amb + ir]);
                pr[ir] = p;
                rs += p;
            }
            *(float2*)&smf[POFF + l * 66 + pco]     = make_float2(pr[0], pr[1]);
            *(float2*)&smf[POFF + l * 66 + pco + 2] = make_float2(pr[2], pr[3]);
            rs += __shfl_xor_sync(0xffffffffu, rs, 1);
            rs += __shfl_xor_sync(0xffffffffu, rs, 2);
            rs += __shfl_xor_sync(0xffffffffu, rs, 4);
            rs += __shfl_xor_sync(0xffffffffu, rs, 8);
            if (tx == 0) smf[DNOFF + l] += rs;
        }
        __syncwarp();   // this warp's P rows (its own ty halves) fully written

        // ---- PV: rr-pairs; P pair loaded 64-bit (swizzled cols), dup in regs
#pragma unroll 2
        for (int rr2 = 0; rr2 < 32; rr2++) {
            const int rr  = rr2 << 1;
            const int rro = rr + ((rr >> 5) << 1);    // P col swizzle for rr
            ull v00 = *(const ull*)&smf[VOFF + rr * 68 + txo];
            ull v01 = *(const ull*)&smf[VOFF + rr * 68 + txo + 2];
            ull v10 = *(const ull*)&smf[VOFF + (rr + 1) * 68 + txo];
            ull v11 = *(const ull*)&smf[VOFF + (rr + 1) * 68 + txo + 2];
#pragma unroll
            for (int il = 0; il < 4; il++) {
                ull p2 = *(const ull*)&smf[POFF + (ty * 4 + il) * 66 + rro];
                float pa, pb;
                upk2(pa, pb, p2);
                ull pa2 = pk2(pa, pa);
                ull pb2 = pk2(pb, pb);
                fma2(pv2[il][0], pa2, v00);
                fma2(pv2[il][1], pa2, v01);
                fma2(pv2[il][0], pb2, v10);
                fma2(pv2[il][1], pb2, v11);
            }
        }
        __syncthreads();                 // all warps done reading V (and P)
        if (c < 15) issue_V((c + 1) * 64);
        CPA_WAIT0();                     // K',E',V' landed
        __syncthreads();
    }

    // ---- write out: out[b, l, h*64 + d] = acc / (eps + denom)
#pragma unroll
    for (int il = 0; il < 4; il++) {
        int l = l0 + ty * 4 + il;
        float dinv = 1.f / (1e-8f + smf[DNOFF + ty * 4 + il]);
        float a0, a1, a2_, a3;
        upk2(a0, a1, pv2[il][0]);
        upk2(a2_, a3, pv2[il][1]);
        float4 o = make_float4(a0 * dinv, a1 * dinv, a2_ * dinv, a3 * dinv);
        *(float4*)&out[((size_t)(b * Sc + l)) * HIDc + h * 64 + tx * 4] = o;
    }
}

// ---------------------------------------------------------------------------
extern "C" void kernel_launch(void* const* d_in, const int* in_sizes, int n_in,
                              void* d_out, int out_size)
{
    const float* hidden = (const float*)d_in[0];
    const float* amask  = (const float*)d_in[1];
    const int*   skim   = (const int*)  d_in[2];
    const float* Wq     = (const float*)d_in[3];
    const float* bq     = (const float*)d_in[4];
    const float* Wk     = (const float*)d_in[5];
    const float* bk     = (const float*)d_in[6];
    const float* Wv     = (const float*)d_in[7];
    const float* bv     = (const float*)d_in[8];
    const float* demb   = (const float*)d_in[9];
    float* out = (float*)d_out;

    dim3 ggrid(8, 32);   // N/128, M/128
    gemm_proj<<<ggrid, 256>>>(hidden, Wq, bq, 0);
    gemm_proj<<<ggrid, 256>>>(hidden, Wk, bk, 1);
    gemm_proj<<<ggrid, 256>>>(hidden, Wv, bv, 2);

    cudaFuncSetAttribute(attn_kernel,
                         cudaFuncAttributeMaxDynamicSharedMemorySize,
                         ATTN_SMEM_BYTES);
    dim3 agrid(Sc / 64, Bc * Hc);
    attn_kernel<<<agrid, 256, ATTN_SMEM_BYTES>>>(amask, skim, demb, out);
}

// round 17
// speedup vs baseline: 1.0288x; 1.0184x over previous
#include <cuda_runtime.h>
#include <math.h>
#include <stdint.h>

// Problem constants
#define Bc   4
#define Sc   1024
#define HIDc 1024
#define Hc   16
#define Dc   64

// Scratch for Q, K, V in [B,H,S,D] layout (16 MB each)
__device__ float g_q[Bc * Hc * Sc * Dc];
__device__ float g_k[Bc * Hc * Sc * Dc];
__device__ float g_v[Bc * Hc * Sc * Dc];

typedef unsigned long long ull;

__device__ __forceinline__ ull pk2(float lo, float hi) {
    ull r;
    asm("mov.b64 %0, {%1, %2};" : "=l"(r) : "f"(lo), "f"(hi));
    return r;
}
__device__ __forceinline__ void upk2(float& lo, float& hi, ull v) {
    asm("mov.b64 {%0, %1}, %2;" : "=f"(lo), "=f"(hi) : "l"(v));
}
__device__ __forceinline__ void fma2(ull& d, ull a, ull b) {
    asm("fma.rn.f32x2 %0, %1, %2, %0;" : "+l"(d) : "l"(a), "l"(b));
}
__device__ __forceinline__ uint32_t smem_u32(const void* p) {
    uint32_t a;
    asm("{ .reg .u64 t; cvta.to.shared.u64 t, %1; cvt.u32.u64 %0, t; }"
        : "=r"(a) : "l"(p));
    return a;
}
__device__ __forceinline__ void cpa8(uint32_t dst, const void* src) {
    asm volatile("cp.async.ca.shared.global [%0], [%1], 8;"
                 :: "r"(dst), "l"(src) : "memory");
}
__device__ __forceinline__ void cpa16(uint32_t dst, const void* src) {
    asm volatile("cp.async.cg.shared.global [%0], [%1], 16;"
                 :: "r"(dst), "l"(src) : "memory");
}
#define CPA_COMMIT() asm volatile("cp.async.commit_group;" ::: "memory")
#define CPA_WAIT0()  asm volatile("cp.async.wait_group 0;" ::: "memory")
#define CPA_WAIT1()  asm volatile("cp.async.wait_group 1;" ::: "memory")

// ---------------------------------------------------------------------------
// Kernel A: projection GEMM  C = X @ W + bias, scattered to [B,H,S,D]
// (proven scalar version — at the FFMA roofline)
// ---------------------------------------------------------------------------
__global__ __launch_bounds__(256) void gemm_proj(const float* __restrict__ X,
                                                 const float* __restrict__ W,
                                                 const float* __restrict__ bias,
                                                 int which)
{
    __shared__ float As[16][132];
    __shared__ float Bs[16][132];
    float* outp = (which == 0) ? g_q : (which == 1) ? g_k : g_v;

    const int tid = threadIdx.x;
    const int m0  = blockIdx.y * 128;
    const int n0  = blockIdx.x * 128;
    const int ty  = tid >> 4;
    const int tx  = tid & 15;

    float acc[8][8];
#pragma unroll
    for (int i = 0; i < 8; i++)
#pragma unroll
        for (int j = 0; j < 8; j++) acc[i][j] = 0.f;

    for (int k0 = 0; k0 < 1024; k0 += 16) {
#pragma unroll
        for (int i = 0; i < 2; i++) {
            int f   = tid + i * 256;
            int row = f >> 2;
            int kc  = (f & 3) << 2;
            float4 va = *(const float4*)(X + (size_t)(m0 + row) * 1024 + k0 + kc);
            As[kc + 0][row] = va.x;
            As[kc + 1][row] = va.y;
            As[kc + 2][row] = va.z;
            As[kc + 3][row] = va.w;
        }
#pragma unroll
        for (int i = 0; i < 2; i++) {
            int f  = tid + i * 256;
            int kr = f >> 5;
            int nc = (f & 31) << 2;
            *(float4*)&Bs[kr][nc] =
                *(const float4*)(W + (size_t)(k0 + kr) * 1024 + n0 + nc);
        }
        __syncthreads();

#pragma unroll
        for (int kk = 0; kk < 16; kk++) {
            float a[8], b[8];
            *(float4*)&a[0] = *(const float4*)&As[kk][ty * 8];
            *(float4*)&a[4] = *(const float4*)&As[kk][ty * 8 + 4];
            *(float4*)&b[0] = *(const float4*)&Bs[kk][tx * 8];
            *(float4*)&b[4] = *(const float4*)&Bs[kk][tx * 8 + 4];
#pragma unroll
            for (int i = 0; i < 8; i++)
#pragma unroll
                for (int j = 0; j < 8; j++)
                    acc[i][j] += a[i] * b[j];
        }
        __syncthreads();
    }

#pragma unroll
    for (int i = 0; i < 8; i++) {
        int m = m0 + ty * 8 + i;
        int b = m >> 10;
        int s = m & 1023;
#pragma unroll
        for (int j = 0; j < 8; j++) {
            int n = n0 + tx * 8 + j;
            int h = n >> 6;
            int d = n & 63;
            outp[(((size_t)(b * Hc + h)) * Sc + s) * Dc + d] = acc[i][j] + bias[n];
        }
    }
}

// ---------------------------------------------------------------------------
// Kernel B: fused attention. 64x64 tiles, 8x4 micro-tile, 128 threads.
// LDS.128 score loads with 4-float-granular monotone rotations,
// cpa16 K/E copies, deferred V-wait cp.async pipeline, fused amsk,
// f32x2 packed FMAs, P/V column swizzles.
// ---------------------------------------------------------------------------
#define ROT4K(r) ((((r) >> 2) & 15) << 2)
#define ROT4E(r) (((r) >> 2) << 2)

#define QOFF  0                     // 64 x 68                  = 4352
#define KOFF  4352                  // 64 x 68 + rot60 + pad    = 4480
#define VOFF  8832                  // 64 x 68 (col swizzle)    = 4352
#define EOFF  13184                 // 127 x 68 + rot124 + pad  = 8768
#define POFF  21952                 // 64 x 66 (col swizzle)    = 4224
#define DNOFF 26176                 // 64
#define AMOFF 26240                 // 1024 (am + log-mask fused)
#define SMEMF 27264
#define ATTN_SMEM_BYTES (SMEMF * 4) // 109056 B (2 CTAs/SM)

__global__ __launch_bounds__(128)
void attn_kernel(const float* __restrict__ attn_mask,
                 const int*   __restrict__ skim,
                 const float* __restrict__ dist_emb,
                 float*       __restrict__ out)
{
    extern __shared__ float smf[];
    const uint32_t smb = smem_u32(smf);
    const int tid = threadIdx.x;
    const int l0  = blockIdx.x * 64;
    const int bh  = blockIdx.y;
    const int b   = bh >> 4;
    const int h   = bh & 15;
    const int ty  = tid >> 4;   // 0..7  -> 8 query rows each
    const int tx  = tid & 15;   // 0..15 -> 4 key cols each

    const float* q = g_q + (size_t)bh * Sc * Dc;
    const float* k = g_k + (size_t)bh * Sc * Dc;
    const float* v = g_v + (size_t)bh * Sc * Dc;

    // ---- async copy emitters (128 threads) ----
    auto issue_KE = [&](int r0n) {
        const float* ksrc = k + (size_t)r0n * 64;
#pragma unroll
        for (int i = 0; i < 8; i++) {        // K: 64 rows x 16 float4
            int u   = tid + i * 128;
            int row = u >> 4;
            int c4  = (u & 15) << 2;
            uint32_t dst = smb + (uint32_t)(KOFF + row * 68 + ROT4K(row) + c4) * 4;
            cpa16(dst, ksrc + row * 64 + c4);
        }
        const float* esrc = dist_emb + (size_t)(l0 - r0n + 960) * 64;
#pragma unroll
        for (int i = 0; i < 16; i++) {       // E: 127 rows x 16 float4
            int u = tid + i * 128;
            if (u < 2032) {
                int row = u >> 4;
                int c4  = (u & 15) << 2;
                uint32_t dst = smb + (uint32_t)(EOFF + row * 68 + ROT4E(row) + c4) * 4;
                cpa16(dst, esrc + (size_t)row * 64 + c4);
            }
        }
        CPA_COMMIT();
    };
    auto issue_V = [&](int r0n) {
        const float* vsrc = v + (size_t)r0n * 64;
#pragma unroll
        for (int i = 0; i < 16; i++) {       // V: 64 rows x 32 8B-units, col swizzle
            int u   = tid + i * 128;
            int row = u >> 5;
            int c2  = (u & 31) << 1;
            uint32_t dst = smb + (uint32_t)(VOFF + row * 68 + c2 + ((c2 >> 5) << 1)) * 4;
            cpa8(dst, vsrc + row * 64 + c2);
        }
        CPA_COMMIT();
    };

    // ---- prologue: chunk-0 K/E/V async, Q tile, fused amsk row ----
    issue_KE(0);
    issue_V(0);
#pragma unroll
    for (int i = 0; i < 8; i++) {
        int f   = tid + i * 128;       // 0..1023 float4s
        int row = f >> 4;
        int c4  = (f & 15) << 2;
        float4 val = *(const float4*)(q + (size_t)(l0 + row) * 64 + c4);
        *(float4*)&smf[QOFF + row * 68 + c4] = val;
    }
#pragma unroll
    for (int i = 0; i < 8; i++) {
        int f = tid + i * 128;
        float am = attn_mask[b * Sc + f];
        smf[AMOFF + f] = am + (skim[b * Sc + f] ? 0.f : -1e30f);
    }
    if (tid < 64) smf[DNOFF + tid] = 0.f;
    CPA_WAIT1();                    // K0,E0 landed (V0 may be pending)
    __syncthreads();

    ull pv2[8][2];
#pragma unroll
    for (int i = 0; i < 8; i++) { pv2[i][0] = 0ull; pv2[i][1] = 0ull; }

    // Hoisted base addresses (chunk-invariant)
    const int jb0 = ty * 8 - tx * 4 + 60;      // in [0,116]
    int ebt[11];
#pragma unroll
    for (int t = 0; t < 11; t++) {
        int r = jb0 + t;                        // in [0,126]
        ebt[t] = EOFF + r * 68 + ROT4E(r);
    }
    const int qb  = QOFF + ty * 8 * 68;
    const int kb  = KOFF + tx * 4 * 68 + (tx << 2);   // ROT4K(4*tx) = 4*tx
    const int txo = tx * 4 + ((tx >> 3) << 1);        // V col swizzle
    const int pco = tx * 4 + ((tx >> 3) << 1);        // P col swizzle

    for (int c = 0; c < 16; c++) {
        // ---- Scores: s[il][ir] = sum_d q*k + q*e, LDS.128 + f32x2
        ull s2[8][4];
#pragma unroll
        for (int i = 0; i < 8; i++)
#pragma unroll
            for (int j = 0; j < 4; j++) s2[i][j] = 0ull;

#pragma unroll 1
        for (int d4 = 0; d4 < 16; d4++) {
            const int d = d4 << 2;
            ulonglong2 q4[8], k4[4], e4[11];
#pragma unroll
            for (int il = 0; il < 8; il++)
                q4[il] = *(const ulonglong2*)&smf[qb + il * 68 + d];
#pragma unroll
            for (int ir = 0; ir < 4; ir++)
                k4[ir] = *(const ulonglong2*)&smf[kb + ir * 68 + d];
#pragma unroll
            for (int t = 0; t < 11; t++)
                e4[t] = *(const ulonglong2*)&smf[ebt[t] + d];
#pragma unroll
            for (int il = 0; il < 8; il++)
#pragma unroll
                for (int ir = 0; ir < 4; ir++) {
                    fma2(s2[il][ir], q4[il].x, k4[ir].x);
                    fma2(s2[il][ir], q4[il].y, k4[ir].y);
                    fma2(s2[il][ir], q4[il].x, e4[il - ir + 3].x);
                    fma2(s2[il][ir], q4[il].y, e4[il - ir + 3].y);
                }
        }
        __syncthreads();                 // all warps done reading K,E
        if (c < 15) issue_KE((c + 1) * 64);   // overlaps softmax + PV

        // ---- probs = exp(s/8 + amsk); store P (swizzled); accumulate denoms
        const int amb = AMOFF + c * 64 + tx * 4;
#pragma unroll
        for (int il = 0; il < 8; il++) {
            int l = ty * 8 + il;
            float rs = 0.f;
            float pr[4];
#pragma unroll
            for (int ir = 0; ir < 4; ir++) {
                float lo, hi;
                upk2(lo, hi, s2[il][ir]);
                float p = __expf((lo + hi) * 0.125f + smf[amb + ir]);
                pr[ir] = p;
                rs += p;
            }
            *(float2*)&smf[POFF + l * 66 + pco]     = make_float2(pr[0], pr[1]);
            *(float2*)&smf[POFF + l * 66 + pco + 2] = make_float2(pr[2], pr[3]);
            rs += __shfl_xor_sync(0xffffffffu, rs, 1);
            rs += __shfl_xor_sync(0xffffffffu, rs, 2);
            rs += __shfl_xor_sync(0xffffffffu, rs, 4);
            rs += __shfl_xor_sync(0xffffffffu, rs, 8);
            if (tx == 0) smf[DNOFF + l] += rs;
        }
        if (c < 15) CPA_WAIT1(); else CPA_WAIT0();   // V(c) landed
        __syncthreads();                              // V visible to all

        // ---- PV: rr-pairs; P pair loaded 64-bit (swizzled cols), dup in regs
#pragma unroll 2
        for (int rr2 = 0; rr2 < 32; rr2++) {
            const int rr  = rr2 << 1;
            const int rro = rr + ((rr >> 5) << 1);    // P col swizzle for rr
            ull v00 = *(const ull*)&smf[VOFF + rr * 68 + txo];
            ull v01 = *(const ull*)&smf[VOFF + rr * 68 + txo + 2];
            ull v10 = *(const ull*)&smf[VOFF + (rr + 1) * 68 + txo];
            ull v11 = *(const ull*)&smf[VOFF + (rr + 1) * 68 + txo + 2];
#pragma unroll
            for (int il = 0; il < 8; il++) {
                ull p2 = *(const ull*)&smf[POFF + (ty * 8 + il) * 66 + rro];
                float pa, pb;
                upk2(pa, pb, p2);
                ull pa2 = pk2(pa, pa);
                ull pb2 = pk2(pb, pb);
                fma2(pv2[il][0], pa2, v00);
                fma2(pv2[il][1], pa2, v01);
                fma2(pv2[il][0], pb2, v10);
                fma2(pv2[il][1], pb2, v11);
            }
        }
        __syncthreads();                 // all warps done reading V (and P)
        if (c < 15) {
            issue_V((c + 1) * 64);
            CPA_WAIT1();                 // K',E' landed (V' may be pending)
            __syncthreads();
        }
    }

    // ---- write out: out[b, l, h*64 + d] = acc / (eps + denom)
#pragma unroll
    for (int il = 0; il < 8; il++) {
        int l = l0 + ty * 8 + il;
        float dinv = 1.f / (1e-8f + smf[DNOFF + ty * 8 + il]);
        float a0, a1, a2_, a3;
        upk2(a0, a1, pv2[il][0]);
        upk2(a2_, a3, pv2[il][1]);
        float4 o = make_float4(a0 * dinv, a1 * dinv, a2_ * dinv, a3 * dinv);
        *(float4*)&out[((size_t)(b * Sc + l)) * HIDc + h * 64 + tx * 4] = o;
    }
}

// ---------------------------------------------------------------------------
extern "C" void kernel_launch(void* const* d_in, const int* in_sizes, int n_in,
                              void* d_out, int out_size)
{
    const float* hidden = (const float*)d_in[0];
    const float* amask  = (const float*)d_in[1];
    const int*   skim   = (const int*)  d_in[2];
    const float* Wq     = (const float*)d_in[3];
    const float* bq     = (const float*)d_in[4];
    const float* Wk     = (const float*)d_in[5];
    const float* bk     = (const float*)d_in[6];
    const float* Wv     = (const float*)d_in[7];
    const float* bv     = (const float*)d_in[8];
    const float* demb   = (const float*)d_in[9];
    float* out = (float*)d_out;

    dim3 ggrid(8, 32);   // N/128, M/128
    gemm_proj<<<ggrid, 256>>>(hidden, Wq, bq, 0);
    gemm_proj<<<ggrid, 256>>>(hidden, Wk, bk, 1);
    gemm_proj<<<ggrid, 256>>>(hidden, Wv, bv, 2);

    cudaFuncSetAttribute(attn_kernel,
                         cudaFuncAttributeMaxDynamicSharedMemorySize,
                         ATTN_SMEM_BYTES);
    dim3 agrid(Sc / 64, Bc * Hc);
    attn_kernel<<<agrid, 128, ATTN_SMEM_BYTES>>>(amask, skim, demb, out);
}